// round 1
// baseline (speedup 1.0000x reference)
#include <cuda_runtime.h>
#include <cuda_bf16.h>
#include <math.h>

// Problem constants
#define TT 2048
#define DD 4096
#define NH 32
#define KH 8
#define HD 128
#define GG (NH/KH)
#define SCALE 0.08838834764831843f   // 1/sqrt(128)

// ---------------- device scratch (no allocs allowed) ----------------
__device__ float g_q [TT * NH * HD];   // 32 MB   q projection (post-RoPE)
__device__ float g_k [TT * KH * HD];   // 8 MB
__device__ float g_v [TT * KH * HD];   // 8 MB
__device__ float g_ao[TT * NH * HD];   // 32 MB   attention output

// ---------------- fp32 SGEMM: C[M,N] = A[M,K] * B[K,N], all row-major ----
// 128x128 block tile, BK=8, 256 threads, 8x8 microtile in 2x2 groups of 4.
__global__ __launch_bounds__(256) void sgemm128(
    const float* __restrict__ A, const float* __restrict__ B,
    float* __restrict__ C, int M, int N, int Kd)
{
    __shared__ float As[8][128];
    __shared__ float Bs[8][128];
    const int tid = threadIdx.x;

    const float* Ab = A + (size_t)blockIdx.y * 128 * Kd;
    const float* Bb = B + (size_t)blockIdx.x * 128;
    float*       Cb = C + (size_t)blockIdx.y * 128 * N + (size_t)blockIdx.x * 128;

    const int ar = tid >> 1, ac = (tid & 1) * 4;      // A tile 128x8
    const int br = tid >> 5, bc = (tid & 31) * 4;     // B tile 8x128
    const int tr = (tid >> 4) * 4;                    // row group base (0..60)
    const int tc = (tid & 15) * 4;                    // col group base (0..60)

    float acc[2][2][4][4];
    #pragma unroll
    for (int a = 0; a < 2; a++)
        #pragma unroll
        for (int b = 0; b < 2; b++)
            #pragma unroll
            for (int i = 0; i < 4; i++)
                #pragma unroll
                for (int j = 0; j < 4; j++) acc[a][b][i][j] = 0.f;

    for (int k0 = 0; k0 < Kd; k0 += 8) {
        float4 a4 = *(const float4*)(Ab + (size_t)ar * Kd + k0 + ac);
        As[ac + 0][ar] = a4.x; As[ac + 1][ar] = a4.y;
        As[ac + 2][ar] = a4.z; As[ac + 3][ar] = a4.w;
        *(float4*)(&Bs[br][bc]) = *(const float4*)(Bb + (size_t)(k0 + br) * N + bc);
        __syncthreads();

        #pragma unroll
        for (int kk = 0; kk < 8; kk++) {
            float ra[2][4], rb[2][4];
            *(float4*)ra[0] = *(const float4*)(&As[kk][tr]);
            *(float4*)ra[1] = *(const float4*)(&As[kk][tr + 64]);
            *(float4*)rb[0] = *(const float4*)(&Bs[kk][tc]);
            *(float4*)rb[1] = *(const float4*)(&Bs[kk][tc + 64]);
            #pragma unroll
            for (int rg = 0; rg < 2; rg++)
                #pragma unroll
                for (int cg = 0; cg < 2; cg++)
                    #pragma unroll
                    for (int i = 0; i < 4; i++)
                        #pragma unroll
                        for (int j = 0; j < 4; j++)
                            acc[rg][cg][i][j] = fmaf(ra[rg][i], rb[cg][j], acc[rg][cg][i][j]);
        }
        __syncthreads();
    }

    #pragma unroll
    for (int rg = 0; rg < 2; rg++)
        #pragma unroll
        for (int i = 0; i < 4; i++) {
            const int row = tr + rg * 64 + i;
            #pragma unroll
            for (int cg = 0; cg < 2; cg++) {
                float4 o = make_float4(acc[rg][cg][i][0], acc[rg][cg][i][1],
                                       acc[rg][cg][i][2], acc[rg][cg][i][3]);
                *(float4*)(Cb + (size_t)row * N + tc + cg * 64) = o;
            }
        }
}

// ---------------- RoPE (split ordering), in place -----------------------
__global__ void rope_kernel(float* __restrict__ buf, const int* __restrict__ pos,
                            int heads)
{
    int idx = blockIdx.x * 256 + threadIdx.x;
    int total = TT * heads * 64;
    if (idx >= total) return;
    int hh = idx & 63;
    int h  = (idx >> 6) % heads;
    int t  = idx / (64 * heads);

    float e   = (float)hh * (1.0f / 64.0f);
    float inv = 1.0f / powf(10000.0f, e);
    float ang = (float)pos[t] * inv;
    float s, c;
    sincosf(ang, &s, &c);

    float* p = buf + ((size_t)t * heads + h) * HD + hh;
    float x1 = p[0], x2 = p[64];
    p[0]  = x1 * c - x2 * s;
    p[64] = x2 * c + x1 * s;
}

// ---------------- fp32 flash attention (causal, GQA) --------------------
// grid (32 qtiles, 32 heads), 256 threads. Tiles: 64 q rows x 64 k rows.
// smem: Qs[64][129] Ks[64][129] Vs[64][132] Ss[64][68]  = 117,248 B dynamic.
#define SQK 129
#define SV  132
#define SS  68
#define FLASH_SMEM ((64*SQK*2 + 64*SV + 64*SS) * 4)

__global__ __launch_bounds__(256) void flash_attn(
    const float* __restrict__ Qv, const float* __restrict__ Kv,
    const float* __restrict__ Vv, float* __restrict__ Ov)
{
    extern __shared__ float sm[];
    float* Qs = sm;
    float* Ks = Qs + 64 * SQK;
    float* Vs = Ks + 64 * SQK;
    float* Ss = Vs + 64 * SV;

    const int tid = threadIdx.x;
    const int qi  = blockIdx.x;          // q tile
    const int n   = blockIdx.y;          // q head
    const int kv  = n >> 2;              // kv head (G=4)
    const int tq0 = qi * 64;

    const float* Qg = Qv + (size_t)tq0 * (NH * HD) + (size_t)n * HD;
    const float* Kg = Kv + (size_t)kv * HD;
    const float* Vg = Vv + (size_t)kv * HD;

    // load Q tile, pre-scaled
    for (int idx = tid; idx < 64 * 32; idx += 256) {
        int r = idx >> 5, c = (idx & 31) * 4;
        float4 v = *(const float4*)(Qg + (size_t)r * (NH * HD) + c);
        float* dst = Qs + r * SQK + c;
        dst[0] = v.x * SCALE; dst[1] = v.y * SCALE;
        dst[2] = v.z * SCALE; dst[3] = v.w * SCALE;
    }

    const int r   = tid >> 2;            // owned output row (0..63)
    const int c4  = tid & 3;
    const int cb  = c4 * 4;              // column base; cols = cb + 16k
    const int qr0 = (tid >> 4) * 4;      // S-compute mapping
    const int kc0 = (tid & 15) * 4;

    float m = -1e30f, l = 0.f;
    float4 o[8];
    #pragma unroll
    for (int k = 0; k < 8; k++) o[k] = make_float4(0.f, 0.f, 0.f, 0.f);

    for (int kt = 0; kt <= qi; kt++) {
        __syncthreads();                 // protect K/V from readers of prev iter
        const int s0 = kt * 64;
        for (int idx = tid; idx < 64 * 32; idx += 256) {
            int rr = idx >> 5, cc = (idx & 31) * 4;
            float4 kk = *(const float4*)(Kg + (size_t)(s0 + rr) * (KH * HD) + cc);
            float* kd = Ks + rr * SQK + cc;
            kd[0] = kk.x; kd[1] = kk.y; kd[2] = kk.z; kd[3] = kk.w;
            float4 vv = *(const float4*)(Vg + (size_t)(s0 + rr) * (KH * HD) + cc);
            *(float4*)(Vs + rr * SV + cc) = vv;
        }
        __syncthreads();

        // S = (Q*scale) K^T  (4x4 per thread)
        float acc[4][4];
        #pragma unroll
        for (int i = 0; i < 4; i++)
            #pragma unroll
            for (int j = 0; j < 4; j++) acc[i][j] = 0.f;

        #pragma unroll 4
        for (int d = 0; d < 128; d++) {
            float qv[4], kk[4];
            #pragma unroll
            for (int i = 0; i < 4; i++) qv[i] = Qs[(qr0 + i) * SQK + d];
            #pragma unroll
            for (int j = 0; j < 4; j++) kk[j] = Ks[(kc0 + j) * SQK + d];
            #pragma unroll
            for (int i = 0; i < 4; i++)
                #pragma unroll
                for (int j = 0; j < 4; j++)
                    acc[i][j] = fmaf(qv[i], kk[j], acc[i][j]);
        }

        const bool diag = (kt == qi);
        #pragma unroll
        for (int i = 0; i < 4; i++) {
            const int tg = tq0 + qr0 + i;
            #pragma unroll
            for (int j = 0; j < 4; j++) {
                float v = acc[i][j];
                if (diag && (s0 + kc0 + j) > tg) v = -1e30f;
                Ss[(qr0 + i) * SS + kc0 + j] = v;
            }
        }
        __syncthreads();

        // online softmax update for row r (4 lanes cooperate, strided j)
        float mt = -1e30f;
        #pragma unroll
        for (int jj = 0; jj < 16; jj++)
            mt = fmaxf(mt, Ss[r * SS + c4 + 4 * jj]);
        mt = fmaxf(mt, __shfl_xor_sync(0xffffffffu, mt, 1));
        mt = fmaxf(mt, __shfl_xor_sync(0xffffffffu, mt, 2));
        const float mn = fmaxf(m, mt);
        const float alpha = __expf(m - mn);
        float lp = 0.f;
        #pragma unroll
        for (int jj = 0; jj < 16; jj++) {
            const int j = c4 + 4 * jj;
            float p = __expf(Ss[r * SS + j] - mn);
            lp += p;
            Ss[r * SS + j] = p;
        }
        lp += __shfl_xor_sync(0xffffffffu, lp, 1);
        lp += __shfl_xor_sync(0xffffffffu, lp, 2);
        l = l * alpha + lp;
        m = mn;
        #pragma unroll
        for (int k = 0; k < 8; k++) {
            o[k].x *= alpha; o[k].y *= alpha; o[k].z *= alpha; o[k].w *= alpha;
        }
        __syncwarp();

        // O += P V  (columns cb + 16k, conflict-free LDS.128)
        #pragma unroll 4
        for (int j = 0; j < 64; j++) {
            const float p = Ss[r * SS + j];
            const float4* vr = (const float4*)(Vs + j * SV + cb);
            #pragma unroll
            for (int k = 0; k < 8; k++) {
                float4 vv = vr[k * 4];
                o[k].x = fmaf(p, vv.x, o[k].x);
                o[k].y = fmaf(p, vv.y, o[k].y);
                o[k].z = fmaf(p, vv.z, o[k].z);
                o[k].w = fmaf(p, vv.w, o[k].w);
            }
        }
    }

    const float inv = 1.0f / l;
    float* Og = Ov + (size_t)(tq0 + r) * (NH * HD) + (size_t)n * HD + cb;
    #pragma unroll
    for (int k = 0; k < 8; k++) {
        float4 v = o[k];
        v.x *= inv; v.y *= inv; v.z *= inv; v.w *= inv;
        *(float4*)(Og + 16 * k) = v;
    }
}

// ---------------- launch ------------------------------------------------
extern "C" void kernel_launch(void* const* d_in, const int* in_sizes, int n_in,
                              void* d_out, int out_size)
{
    const float* x   = (const float*)d_in[0];
    const int*   pos = (const int*)  d_in[1];
    const float* w_q = (const float*)d_in[2];
    const float* w_k = (const float*)d_in[3];
    const float* w_v = (const float*)d_in[4];
    const float* w_o = (const float*)d_in[5];
    float* out = (float*)d_out;

    float *q, *k, *v, *ao;
    cudaGetSymbolAddress((void**)&q,  g_q);
    cudaGetSymbolAddress((void**)&k,  g_k);
    cudaGetSymbolAddress((void**)&v,  g_v);
    cudaGetSymbolAddress((void**)&ao, g_ao);

    cudaFuncSetAttribute(flash_attn, cudaFuncAttributeMaxDynamicSharedMemorySize,
                         FLASH_SMEM);

    // QKV projections
    sgemm128<<<dim3((NH*HD)/128, TT/128), 256>>>(x, w_q, q, TT, NH*HD, DD);
    sgemm128<<<dim3((KH*HD)/128, TT/128), 256>>>(x, w_k, k, TT, KH*HD, DD);
    sgemm128<<<dim3((KH*HD)/128, TT/128), 256>>>(x, w_v, v, TT, KH*HD, DD);

    // RoPE
    rope_kernel<<<(TT*NH*64 + 255)/256, 256>>>(q, pos, NH);
    rope_kernel<<<(TT*KH*64 + 255)/256, 256>>>(k, pos, KH);

    // causal GQA flash attention
    flash_attn<<<dim3(TT/64, NH), 256, FLASH_SMEM>>>(q, k, v, ao);

    // output projection
    sgemm128<<<dim3(DD/128, TT/128), 256>>>(ao, w_o, out, TT, DD, DD);
}

// round 3
// speedup vs baseline: 1.8364x; 1.8364x over previous
#include <cuda_runtime.h>
#include <cuda_bf16.h>
#include <cstdint>
#include <math.h>

// Problem constants
#define TT 2048
#define DD 4096
#define NH 32
#define KH 8
#define HD 128
#define SCALE 0.08838834764831843f   // 1/sqrt(128)

// ====================== PTX helpers (base sm_103-legal only) ======================
__device__ __forceinline__ uint32_t smem_to_u32(const void* p) {
    uint32_t a;
    asm("{ .reg .u64 t; cvta.to.shared.u64 t, %1; cvt.u32.u64 %0, t; }" : "=r"(a) : "l"(p));
    return a;
}
#define CP16(sa, ga) \
    asm volatile("cp.async.cg.shared.global [%0], [%1], 16;" :: "r"(sa), "l"(ga) : "memory")
#define CP_COMMIT() asm volatile("cp.async.commit_group;" ::: "memory")
#define CP_WAIT(n)  asm volatile("cp.async.wait_group %0;" :: "n"(n) : "memory")
#define LDSM4(r, a) \
    asm volatile("ldmatrix.sync.aligned.m8n8.x4.shared.b16 {%0,%1,%2,%3}, [%4];" \
        : "=r"((r)[0]), "=r"((r)[1]), "=r"((r)[2]), "=r"((r)[3]) : "r"(a))
#define LDSM2(r, a) \
    asm volatile("ldmatrix.sync.aligned.m8n8.x2.shared.b16 {%0,%1}, [%2];" \
        : "=r"((r)[0]), "=r"((r)[1]) : "r"(a))
#define MMA16816(d, a, b) \
    asm volatile("mma.sync.aligned.m16n8k16.row.col.f32.bf16.bf16.f32 " \
        "{%0,%1,%2,%3}, {%4,%5,%6,%7}, {%8,%9}, {%0,%1,%2,%3};" \
        : "+f"((d)[0]), "+f"((d)[1]), "+f"((d)[2]), "+f"((d)[3]) \
        : "r"((a)[0]), "r"((a)[1]), "r"((a)[2]), "r"((a)[3]), "r"((b)[0]), "r"((b)[1]))

// ====================== device scratch ======================
__device__ float g_q [TT * NH * HD];
__device__ float g_k [TT * KH * HD];
__device__ float g_v [TT * KH * HD];
__device__ float g_ao[TT * NH * HD];

__device__ __nv_bfloat16 g_xhi [TT * DD],  g_xlo [TT * DD];
__device__ __nv_bfloat16 g_aohi[TT * DD],  g_aolo[TT * DD];
__device__ __nv_bfloat16 g_wqhi[DD * DD],  g_wqlo[DD * DD];     // transposed [N][K]
__device__ __nv_bfloat16 g_wkhi[KH*HD*DD], g_wklo[KH*HD*DD];
__device__ __nv_bfloat16 g_wvhi[KH*HD*DD], g_wvlo[KH*HD*DD];
__device__ __nv_bfloat16 g_wohi[DD * DD],  g_wolo[DD * DD];

// ====================== fp32 -> bf16 hi/lo split ======================
__global__ void split_f32(const float* __restrict__ s, __nv_bfloat16* __restrict__ hi,
                          __nv_bfloat16* __restrict__ lo, int n4)
{
    int i = blockIdx.x * 256 + threadIdx.x;
    if (i >= n4) return;
    float4 f = ((const float4*)s)[i];
    float v[4] = {f.x, f.y, f.z, f.w};
    __align__(8) __nv_bfloat16 h[4], l[4];
    #pragma unroll
    for (int j = 0; j < 4; j++) {
        h[j] = __float2bfloat16(v[j]);
        l[j] = __float2bfloat16(v[j] - __bfloat162float(h[j]));
    }
    *(uint2*)(hi + 4 * (size_t)i) = *(uint2*)h;
    *(uint2*)(lo + 4 * (size_t)i) = *(uint2*)l;
}

// transpose + split: src fp32 [R,C] -> hi/lo bf16 [C,R]
__global__ __launch_bounds__(256) void splitT_f32(const float* __restrict__ s,
    __nv_bfloat16* __restrict__ hi, __nv_bfloat16* __restrict__ lo, int R, int C)
{
    __shared__ float t[32][33];
    int bx = blockIdx.x * 32, by = blockIdx.y * 32;
    int tx = threadIdx.x & 31, ty = threadIdx.x >> 5;
    #pragma unroll
    for (int j = 0; j < 4; j++)
        t[ty + 8*j][tx] = s[(size_t)(by + ty + 8*j) * C + bx + tx];
    __syncthreads();
    #pragma unroll
    for (int j = 0; j < 4; j++) {
        float f = t[tx][ty + 8*j];
        __nv_bfloat16 h = __float2bfloat16(f);
        float r = f - __bfloat162float(h);
        size_t o = (size_t)(bx + ty + 8*j) * R + by + tx;
        hi[o] = h;
        lo[o] = __float2bfloat16(r);
    }
}

// ====================== mma.sync bf16x3 GEMM ======================
// C[M,N] = A[M,K] x BT[N,K]^T with A=Ahi+Alo, B=Bhi+Blo (3-term product).
// 128x128 CTA tile, BK=32, 8 warps (2x4), warp tile 64x32, cp.async 2-stage.
#define SROWB 80                       // smem row stride in bytes (32 halves + 8 pad)
#define TILE_B (128 * SROWB)           // 10240 B per matrix tile
#define STAGE_B (4 * TILE_B)           // Ahi | Alo | Bhi | Blo
#define GEMM_SMEM (2 * STAGE_B)        // 81920 B

__global__ __launch_bounds__(256) void gemm_bf3(
    const __nv_bfloat16* __restrict__ Ahi, const __nv_bfloat16* __restrict__ Alo,
    const __nv_bfloat16* __restrict__ BThi, const __nv_bfloat16* __restrict__ BTlo,
    float* __restrict__ C, int M, int N, int Kd)
{
    extern __shared__ char smraw[];
    const uint32_t sbase = smem_to_u32(smraw);
    const int tid = threadIdx.x, lane = tid & 31, wid = tid >> 5;
    const int wm = wid >> 2, wn = wid & 3;

    const __nv_bfloat16* pAh = Ahi  + (size_t)blockIdx.y * 128 * Kd;
    const __nv_bfloat16* pAl = Alo  + (size_t)blockIdx.y * 128 * Kd;
    const __nv_bfloat16* pBh = BThi + (size_t)blockIdx.x * 128 * Kd;
    const __nv_bfloat16* pBl = BTlo + (size_t)blockIdx.x * 128 * Kd;

    const int lrow  = tid >> 2;             // 0..63 (x2 halves of tile)
    const int lcolh = (tid & 3) * 8;        // halves within a 32-half row
    const uint32_t lso = (tid & 3) * 16;    // byte offset within row

    float acc[4][4][4];
    #pragma unroll
    for (int mt = 0; mt < 4; mt++)
        #pragma unroll
        for (int nt = 0; nt < 4; nt++)
            #pragma unroll
            for (int q = 0; q < 4; q++) acc[mt][nt][q] = 0.f;

    const int nst = Kd >> 5;   // BK=32

    // prologue: stage 0
    {
        uint32_t st = sbase;
        #pragma unroll
        for (int i = 0; i < 2; i++) {
            int row = lrow + 64 * i;
            uint32_t so = st + (uint32_t)row * SROWB + lso;
            size_t go = (size_t)row * Kd + lcolh;
            CP16(so,              pAh + go);
            CP16(so + TILE_B,     pAl + go);
            CP16(so + 2*TILE_B,   pBh + go);
            CP16(so + 3*TILE_B,   pBl + go);
        }
        CP_COMMIT();
    }

    for (int s = 0; s < nst; s++) {
        if (s + 1 < nst) {
            const int k0 = (s + 1) << 5;
            uint32_t st = sbase + ((s + 1) & 1) * STAGE_B;
            #pragma unroll
            for (int i = 0; i < 2; i++) {
                int row = lrow + 64 * i;
                uint32_t so = st + (uint32_t)row * SROWB + lso;
                size_t go = (size_t)row * Kd + k0 + lcolh;
                CP16(so,              pAh + go);
                CP16(so + TILE_B,     pAl + go);
                CP16(so + 2*TILE_B,   pBh + go);
                CP16(so + 3*TILE_B,   pBl + go);
            }
            CP_COMMIT();
            CP_WAIT(1);
        } else {
            CP_WAIT(0);
        }
        __syncthreads();

        uint32_t st = sbase + (s & 1) * STAGE_B;
        const uint32_t aAddr = st + (uint32_t)(wm * 64 + (lane & 15)) * SROWB
                             + (lane >> 4) * 16;
        const uint32_t bAddr = st + 2 * TILE_B
                             + (uint32_t)(wn * 32 + (lane & 7)) * SROWB
                             + ((lane >> 3) & 1) * 16;

        #pragma unroll
        for (int kk = 0; kk < 2; kk++) {
            uint32_t ah[4][4], al[4][4], bb[4][2];
            #pragma unroll
            for (int mt = 0; mt < 4; mt++)
                LDSM4(ah[mt], aAddr + mt * 16 * SROWB + kk * 32);
            #pragma unroll
            for (int nt = 0; nt < 4; nt++)
                LDSM2(bb[nt], bAddr + nt * 8 * SROWB + kk * 32);
            #pragma unroll
            for (int mt = 0; mt < 4; mt++)
                #pragma unroll
                for (int nt = 0; nt < 4; nt++)
                    MMA16816(acc[mt][nt], ah[mt], bb[nt]);      // Ahi * Bhi

            #pragma unroll
            for (int mt = 0; mt < 4; mt++)
                LDSM4(al[mt], aAddr + TILE_B + mt * 16 * SROWB + kk * 32);
            #pragma unroll
            for (int mt = 0; mt < 4; mt++)
                #pragma unroll
                for (int nt = 0; nt < 4; nt++)
                    MMA16816(acc[mt][nt], al[mt], bb[nt]);      // Alo * Bhi

            #pragma unroll
            for (int nt = 0; nt < 4; nt++)
                LDSM2(bb[nt], bAddr + TILE_B + nt * 8 * SROWB + kk * 32);
            #pragma unroll
            for (int mt = 0; mt < 4; mt++)
                #pragma unroll
                for (int nt = 0; nt < 4; nt++)
                    MMA16816(acc[mt][nt], ah[mt], bb[nt]);      // Ahi * Blo
        }
        __syncthreads();
    }

    // epilogue
    const int rb = blockIdx.y * 128 + wm * 64 + (lane >> 2);
    const int cb = blockIdx.x * 128 + wn * 32 + (lane & 3) * 2;
    #pragma unroll
    for (int mt = 0; mt < 4; mt++) {
        #pragma unroll
        for (int nt = 0; nt < 4; nt++) {
            const int row = rb + mt * 16;
            const int col = cb + nt * 8;
            *(float2*)(C + (size_t)row * N + col) =
                make_float2(acc[mt][nt][0], acc[mt][nt][1]);
            *(float2*)(C + (size_t)(row + 8) * N + col) =
                make_float2(acc[mt][nt][2], acc[mt][nt][3]);
        }
    }
}

// ====================== RoPE (split ordering), in place ======================
__global__ void rope_kernel(float* __restrict__ buf, const int* __restrict__ pos, int heads)
{
    int idx = blockIdx.x * 256 + threadIdx.x;
    int total = TT * heads * 64;
    if (idx >= total) return;
    int hh = idx & 63;
    int h  = (idx >> 6) % heads;
    int t  = idx / (64 * heads);

    float e   = (float)hh * (1.0f / 64.0f);
    float inv = 1.0f / powf(10000.0f, e);
    float ang = (float)pos[t] * inv;
    float s, c;
    sincosf(ang, &s, &c);

    float* p = buf + ((size_t)t * heads + h) * HD + hh;
    float x1 = p[0], x2 = p[64];
    p[0]  = x1 * c - x2 * s;
    p[64] = x2 * c + x1 * s;
}

// ====================== fp32 flash attention (causal, GQA) ======================
#define SQK 129
#define SV  132
#define SS  68
#define FLASH_SMEM ((64*SQK*2 + 64*SV + 64*SS) * 4)

__global__ __launch_bounds__(256) void flash_attn(
    const float* __restrict__ Qv, const float* __restrict__ Kv,
    const float* __restrict__ Vv, float* __restrict__ Ov)
{
    extern __shared__ float sm[];
    float* Qs = sm;
    float* Ks = Qs + 64 * SQK;
    float* Vs = Ks + 64 * SQK;
    float* Ss = Vs + 64 * SV;

    const int tid = threadIdx.x;
    const int qi  = blockIdx.x;
    const int n   = blockIdx.y;
    const int kv  = n >> 2;
    const int tq0 = qi * 64;

    const float* Qg = Qv + (size_t)tq0 * (NH * HD) + (size_t)n * HD;
    const float* Kg = Kv + (size_t)kv * HD;
    const float* Vg = Vv + (size_t)kv * HD;

    for (int idx = tid; idx < 64 * 32; idx += 256) {
        int r = idx >> 5, c = (idx & 31) * 4;
        float4 v = *(const float4*)(Qg + (size_t)r * (NH * HD) + c);
        float* dst = Qs + r * SQK + c;
        dst[0] = v.x * SCALE; dst[1] = v.y * SCALE;
        dst[2] = v.z * SCALE; dst[3] = v.w * SCALE;
    }

    const int r   = tid >> 2;
    const int c4  = tid & 3;
    const int cb  = c4 * 4;
    const int qr0 = (tid >> 4) * 4;
    const int kc0 = (tid & 15) * 4;

    float m = -1e30f, l = 0.f;
    float4 o[8];
    #pragma unroll
    for (int k = 0; k < 8; k++) o[k] = make_float4(0.f, 0.f, 0.f, 0.f);

    for (int kt = 0; kt <= qi; kt++) {
        __syncthreads();
        const int s0 = kt * 64;
        for (int idx = tid; idx < 64 * 32; idx += 256) {
            int rr = idx >> 5, cc = (idx & 31) * 4;
            float4 kk = *(const float4*)(Kg + (size_t)(s0 + rr) * (KH * HD) + cc);
            float* kd = Ks + rr * SQK + cc;
            kd[0] = kk.x; kd[1] = kk.y; kd[2] = kk.z; kd[3] = kk.w;
            float4 vv = *(const float4*)(Vg + (size_t)(s0 + rr) * (KH * HD) + cc);
            *(float4*)(Vs + rr * SV + cc) = vv;
        }
        __syncthreads();

        float acc[4][4];
        #pragma unroll
        for (int i = 0; i < 4; i++)
            #pragma unroll
            for (int j = 0; j < 4; j++) acc[i][j] = 0.f;

        #pragma unroll 4
        for (int d = 0; d < 128; d++) {
            float qv[4], kk[4];
            #pragma unroll
            for (int i = 0; i < 4; i++) qv[i] = Qs[(qr0 + i) * SQK + d];
            #pragma unroll
            for (int j = 0; j < 4; j++) kk[j] = Ks[(kc0 + j) * SQK + d];
            #pragma unroll
            for (int i = 0; i < 4; i++)
                #pragma unroll
                for (int j = 0; j < 4; j++)
                    acc[i][j] = fmaf(qv[i], kk[j], acc[i][j]);
        }

        const bool diag = (kt == qi);
        #pragma unroll
        for (int i = 0; i < 4; i++) {
            const int tg = tq0 + qr0 + i;
            #pragma unroll
            for (int j = 0; j < 4; j++) {
                float v = acc[i][j];
                if (diag && (s0 + kc0 + j) > tg) v = -1e30f;
                Ss[(qr0 + i) * SS + kc0 + j] = v;
            }
        }
        __syncthreads();

        float mt = -1e30f;
        #pragma unroll
        for (int jj = 0; jj < 16; jj++)
            mt = fmaxf(mt, Ss[r * SS + c4 + 4 * jj]);
        mt = fmaxf(mt, __shfl_xor_sync(0xffffffffu, mt, 1));
        mt = fmaxf(mt, __shfl_xor_sync(0xffffffffu, mt, 2));
        const float mn = fmaxf(m, mt);
        const float alpha = __expf(m - mn);
        float lp = 0.f;
        #pragma unroll
        for (int jj = 0; jj < 16; jj++) {
            const int j = c4 + 4 * jj;
            float p = __expf(Ss[r * SS + j] - mn);
            lp += p;
            Ss[r * SS + j] = p;
        }
        lp += __shfl_xor_sync(0xffffffffu, lp, 1);
        lp += __shfl_xor_sync(0xffffffffu, lp, 2);
        l = l * alpha + lp;
        m = mn;
        #pragma unroll
        for (int k = 0; k < 8; k++) {
            o[k].x *= alpha; o[k].y *= alpha; o[k].z *= alpha; o[k].w *= alpha;
        }
        __syncwarp();

        #pragma unroll 4
        for (int j = 0; j < 64; j++) {
            const float p = Ss[r * SS + j];
            const float4* vr = (const float4*)(Vs + j * SV + cb);
            #pragma unroll
            for (int k = 0; k < 8; k++) {
                float4 vv = vr[k * 4];
                o[k].x = fmaf(p, vv.x, o[k].x);
                o[k].y = fmaf(p, vv.y, o[k].y);
                o[k].z = fmaf(p, vv.z, o[k].z);
                o[k].w = fmaf(p, vv.w, o[k].w);
            }
        }
    }

    const float inv = 1.0f / l;
    float* Og = Ov + (size_t)(tq0 + r) * (NH * HD) + (size_t)n * HD + cb;
    #pragma unroll
    for (int k = 0; k < 8; k++) {
        float4 v = o[k];
        v.x *= inv; v.y *= inv; v.z *= inv; v.w *= inv;
        *(float4*)(Og + 16 * k) = v;
    }
}

// ====================== launch ======================
extern "C" void kernel_launch(void* const* d_in, const int* in_sizes, int n_in,
                              void* d_out, int out_size)
{
    const float* x   = (const float*)d_in[0];
    const int*   pos = (const int*)  d_in[1];
    const float* w_q = (const float*)d_in[2];
    const float* w_k = (const float*)d_in[3];
    const float* w_v = (const float*)d_in[4];
    const float* w_o = (const float*)d_in[5];
    float* out = (float*)d_out;

    float *q, *k, *v, *ao;
    cudaGetSymbolAddress((void**)&q,  g_q);
    cudaGetSymbolAddress((void**)&k,  g_k);
    cudaGetSymbolAddress((void**)&v,  g_v);
    cudaGetSymbolAddress((void**)&ao, g_ao);
    __nv_bfloat16 *xhi, *xlo, *aohi, *aolo, *wqhi, *wqlo, *wkhi, *wklo, *wvhi, *wvlo, *wohi, *wolo;
    cudaGetSymbolAddress((void**)&xhi,  g_xhi);  cudaGetSymbolAddress((void**)&xlo,  g_xlo);
    cudaGetSymbolAddress((void**)&aohi, g_aohi); cudaGetSymbolAddress((void**)&aolo, g_aolo);
    cudaGetSymbolAddress((void**)&wqhi, g_wqhi); cudaGetSymbolAddress((void**)&wqlo, g_wqlo);
    cudaGetSymbolAddress((void**)&wkhi, g_wkhi); cudaGetSymbolAddress((void**)&wklo, g_wklo);
    cudaGetSymbolAddress((void**)&wvhi, g_wvhi); cudaGetSymbolAddress((void**)&wvlo, g_wvlo);
    cudaGetSymbolAddress((void**)&wohi, g_wohi); cudaGetSymbolAddress((void**)&wolo, g_wolo);

    cudaFuncSetAttribute(flash_attn, cudaFuncAttributeMaxDynamicSharedMemorySize, FLASH_SMEM);
    cudaFuncSetAttribute(gemm_bf3,   cudaFuncAttributeMaxDynamicSharedMemorySize, GEMM_SMEM);

    // split/transposed operands
    split_f32<<<(TT*DD/4 + 255)/256, 256>>>(x, xhi, xlo, TT*DD/4);
    splitT_f32<<<dim3(DD/32, DD/32),       256>>>(w_q, wqhi, wqlo, DD, DD);
    splitT_f32<<<dim3(KH*HD/32, DD/32),    256>>>(w_k, wkhi, wklo, DD, KH*HD);
    splitT_f32<<<dim3(KH*HD/32, DD/32),    256>>>(w_v, wvhi, wvlo, DD, KH*HD);
    splitT_f32<<<dim3(DD/32, DD/32),       256>>>(w_o, wohi, wolo, DD, DD);

    // QKV projections (mma.sync bf16x3)
    gemm_bf3<<<dim3(32, 16), 256, GEMM_SMEM>>>(xhi, xlo, wqhi, wqlo, q, TT, NH*HD, DD);
    gemm_bf3<<<dim3(8, 16),  256, GEMM_SMEM>>>(xhi, xlo, wkhi, wklo, k, TT, KH*HD, DD);
    gemm_bf3<<<dim3(8, 16),  256, GEMM_SMEM>>>(xhi, xlo, wvhi, wvlo, v, TT, KH*HD, DD);

    // RoPE
    rope_kernel<<<(TT*NH*64 + 255)/256, 256>>>(q, pos, NH);
    rope_kernel<<<(TT*KH*64 + 255)/256, 256>>>(k, pos, KH);

    // causal GQA flash attention (fp32)
    flash_attn<<<dim3(TT/64, NH), 256, FLASH_SMEM>>>(q, k, v, ao);

    // output projection
    split_f32<<<(TT*DD/4 + 255)/256, 256>>>(ao, aohi, aolo, TT*DD/4);
    gemm_bf3<<<dim3(32, 16), 256, GEMM_SMEM>>>(aohi, aolo, wohi, wolo, out, TT, DD, DD);
}

// round 5
// speedup vs baseline: 4.0785x; 2.2209x over previous
#include <cuda_runtime.h>
#include <cuda_fp16.h>
#include <cstdint>
#include <math.h>

// Problem constants
#define TT 2048
#define DD 4096
#define NH 32
#define KH 8
#define HD 128
#define SCALE 0.08838834764831843f   // 1/sqrt(128)

// ====================== PTX helpers (base sm_103-legal only) ======================
__device__ __forceinline__ uint32_t smem_to_u32(const void* p) {
    uint32_t a;
    asm("{ .reg .u64 t; cvta.to.shared.u64 t, %1; cvt.u32.u64 %0, t; }" : "=r"(a) : "l"(p));
    return a;
}
#define CP16(sa, ga) \
    asm volatile("cp.async.cg.shared.global [%0], [%1], 16;" :: "r"(sa), "l"(ga) : "memory")
#define CP_COMMIT() asm volatile("cp.async.commit_group;" ::: "memory")
#define CP_WAIT(n)  asm volatile("cp.async.wait_group %0;" :: "n"(n) : "memory")
#define LDSM4(r, a) \
    asm volatile("ldmatrix.sync.aligned.m8n8.x4.shared.b16 {%0,%1,%2,%3}, [%4];" \
        : "=r"((r)[0]), "=r"((r)[1]), "=r"((r)[2]), "=r"((r)[3]) : "r"(a))
#define LDSM2(r, a) \
    asm volatile("ldmatrix.sync.aligned.m8n8.x2.shared.b16 {%0,%1}, [%2];" \
        : "=r"((r)[0]), "=r"((r)[1]) : "r"(a))
#define LDSM2T(r, a) \
    asm volatile("ldmatrix.sync.aligned.m8n8.x2.trans.shared.b16 {%0,%1}, [%2];" \
        : "=r"((r)[0]), "=r"((r)[1]) : "r"(a))
#define MMAH(d, a, b) \
    asm volatile("mma.sync.aligned.m16n8k16.row.col.f32.f16.f16.f32 " \
        "{%0,%1,%2,%3}, {%4,%5,%6,%7}, {%8,%9}, {%0,%1,%2,%3};" \
        : "+f"((d)[0]), "+f"((d)[1]), "+f"((d)[2]), "+f"((d)[3]) \
        : "r"((a)[0]), "r"((a)[1]), "r"((a)[2]), "r"((a)[3]), "r"((b)[0]), "r"((b)[1]))

// ====================== device scratch ======================
__device__ float  g_q [TT * NH * HD];
__device__ float  g_k [TT * KH * HD];
__device__ float  g_v [TT * KH * HD];

__device__ __half g_xh [TT * DD],  g_xl [TT * DD];
__device__ __half g_aoh[TT * DD],  g_aol[TT * DD];
__device__ __half g_wqT[DD * DD];                 // transposed [N][K] fp16
__device__ __half g_wkT[KH*HD * DD];
__device__ __half g_wvT[KH*HD * DD];
__device__ __half g_woT[DD * DD];
__device__ __half g_qh [TT * NH * HD], g_ql [TT * NH * HD];
__device__ __half g_kh [TT * KH * HD];
__device__ __half g_vh [TT * KH * HD];

// ====================== fp32 -> fp16 hi/lo split ======================
__global__ void split_f32h(const float* __restrict__ s, __half* __restrict__ hi,
                           __half* __restrict__ lo, int n4)
{
    int i = blockIdx.x * 256 + threadIdx.x;
    if (i >= n4) return;
    float4 f = ((const float4*)s)[i];
    float v[4] = {f.x, f.y, f.z, f.w};
    __align__(8) __half h[4], l[4];
    #pragma unroll
    for (int j = 0; j < 4; j++) {
        h[j] = __float2half_rn(v[j]);
        l[j] = __float2half_rn(v[j] - __half2float(h[j]));
    }
    *(uint2*)(hi + 4 * (size_t)i) = *(uint2*)h;
    *(uint2*)(lo + 4 * (size_t)i) = *(uint2*)l;
}

// transpose fp32 [R,C] -> single fp16 [C,R]
__global__ __launch_bounds__(256) void transT_f16(const float* __restrict__ s,
    __half* __restrict__ d, int R, int C)
{
    __shared__ float t[32][33];
    int bx = blockIdx.x * 32, by = blockIdx.y * 32;
    int tx = threadIdx.x & 31, ty = threadIdx.x >> 5;
    #pragma unroll
    for (int j = 0; j < 4; j++)
        t[ty + 8*j][tx] = s[(size_t)(by + ty + 8*j) * C + bx + tx];
    __syncthreads();
    #pragma unroll
    for (int j = 0; j < 4; j++)
        d[(size_t)(bx + ty + 8*j) * R + by + tx] = __float2half_rn(t[tx][ty + 8*j]);
}

// ====================== mma.sync fp16x2 GEMM ======================
// C[M,N] = (Ahi+Alo)[M,K] x BT[N,K]^T, B single fp16.
// 128x128 CTA tile, BK=32, 8 warps, warp tile 64x32, cp.async 2-stage.
#define SROWB 80                       // smem row stride bytes (32 halves + pad)
#define TILE_B (128 * SROWB)           // 10240
#define STAGE_B (3 * TILE_B)           // Ahi | Alo | B
#define GEMM_SMEM (2 * STAGE_B)        // 61440

__global__ __launch_bounds__(256) void gemm_fh2(
    const __half* __restrict__ Ahi, const __half* __restrict__ Alo,
    const __half* __restrict__ BT, float* __restrict__ C, int M, int N, int Kd)
{
    extern __shared__ char smraw[];
    const uint32_t sbase = smem_to_u32(smraw);
    const int tid = threadIdx.x, lane = tid & 31, wid = tid >> 5;
    const int wm = wid >> 2, wn = wid & 3;

    const __half* pAh = Ahi + (size_t)blockIdx.y * 128 * Kd;
    const __half* pAl = Alo + (size_t)blockIdx.y * 128 * Kd;
    const __half* pB  = BT  + (size_t)blockIdx.x * 128 * Kd;

    const int lrow  = tid >> 2;
    const int lcolh = (tid & 3) * 8;
    const uint32_t lso = (tid & 3) * 16;

    float acc[4][4][4];
    #pragma unroll
    for (int mt = 0; mt < 4; mt++)
        #pragma unroll
        for (int nt = 0; nt < 4; nt++)
            #pragma unroll
            for (int q = 0; q < 4; q++) acc[mt][nt][q] = 0.f;

    const int nst = Kd >> 5;

    {   // prologue stage 0
        #pragma unroll
        for (int i = 0; i < 2; i++) {
            int row = lrow + 64 * i;
            uint32_t so = sbase + (uint32_t)row * SROWB + lso;
            size_t go = (size_t)row * Kd + lcolh;
            CP16(so,            pAh + go);
            CP16(so + TILE_B,   pAl + go);
            CP16(so + 2*TILE_B, pB  + go);
        }
        CP_COMMIT();
    }

    for (int s = 0; s < nst; s++) {
        if (s + 1 < nst) {
            const int k0 = (s + 1) << 5;
            uint32_t st = sbase + ((s + 1) & 1) * STAGE_B;
            #pragma unroll
            for (int i = 0; i < 2; i++) {
                int row = lrow + 64 * i;
                uint32_t so = st + (uint32_t)row * SROWB + lso;
                size_t go = (size_t)row * Kd + k0 + lcolh;
                CP16(so,            pAh + go);
                CP16(so + TILE_B,   pAl + go);
                CP16(so + 2*TILE_B, pB  + go);
            }
            CP_COMMIT();
            CP_WAIT(1);
        } else {
            CP_WAIT(0);
        }
        __syncthreads();

        uint32_t st = sbase + (s & 1) * STAGE_B;
        const uint32_t aAddr = st + (uint32_t)(wm * 64 + (lane & 15)) * SROWB
                             + (lane >> 4) * 16;
        const uint32_t bAddr = st + 2 * TILE_B
                             + (uint32_t)(wn * 32 + (lane & 7)) * SROWB
                             + ((lane >> 3) & 1) * 16;

        #pragma unroll
        for (int kk = 0; kk < 2; kk++) {
            uint32_t ah[4][4], al[4][4], bb[4][2];
            #pragma unroll
            for (int mt = 0; mt < 4; mt++)
                LDSM4(ah[mt], aAddr + mt * 16 * SROWB + kk * 32);
            #pragma unroll
            for (int nt = 0; nt < 4; nt++)
                LDSM2(bb[nt], bAddr + nt * 8 * SROWB + kk * 32);
            #pragma unroll
            for (int mt = 0; mt < 4; mt++)
                #pragma unroll
                for (int nt = 0; nt < 4; nt++)
                    MMAH(acc[mt][nt], ah[mt], bb[nt]);          // Ahi * B
            #pragma unroll
            for (int mt = 0; mt < 4; mt++)
                LDSM4(al[mt], aAddr + TILE_B + mt * 16 * SROWB + kk * 32);
            #pragma unroll
            for (int mt = 0; mt < 4; mt++)
                #pragma unroll
                for (int nt = 0; nt < 4; nt++)
                    MMAH(acc[mt][nt], al[mt], bb[nt]);          // Alo * B
        }
        __syncthreads();
    }

    const int rb = blockIdx.y * 128 + wm * 64 + (lane >> 2);
    const int cb = blockIdx.x * 128 + wn * 32 + (lane & 3) * 2;
    #pragma unroll
    for (int mt = 0; mt < 4; mt++)
        #pragma unroll
        for (int nt = 0; nt < 4; nt++) {
            const int row = rb + mt * 16;
            const int col = cb + nt * 8;
            *(float2*)(C + (size_t)row * N + col) =
                make_float2(acc[mt][nt][0], acc[mt][nt][1]);
            *(float2*)(C + (size_t)(row + 8) * N + col) =
                make_float2(acc[mt][nt][2], acc[mt][nt][3]);
        }
}

// ====================== RoPE + fp16 outputs ======================
__global__ void rope_q(const float* __restrict__ src, const int* __restrict__ pos,
                       __half* __restrict__ qh, __half* __restrict__ ql)
{
    int idx = blockIdx.x * 256 + threadIdx.x;
    if (idx >= TT * NH * 64) return;
    int hh = idx & 63;
    int h  = (idx >> 6) % NH;
    int t  = idx / (64 * NH);

    float e   = (float)hh * (1.0f / 64.0f);
    float inv = 1.0f / powf(10000.0f, e);
    float ang = (float)pos[t] * inv;
    float s, c;
    sincosf(ang, &s, &c);

    size_t base = ((size_t)t * NH + h) * HD + hh;
    float x1 = src[base], x2 = src[base + 64];
    float y1 = (x1 * c - x2 * s) * SCALE;
    float y2 = (x2 * c + x1 * s) * SCALE;
    __half h1 = __float2half_rn(y1), h2 = __float2half_rn(y2);
    qh[base]      = h1;  ql[base]      = __float2half_rn(y1 - __half2float(h1));
    qh[base + 64] = h2;  ql[base + 64] = __float2half_rn(y2 - __half2float(h2));
}

__global__ void rope_k(const float* __restrict__ src, const int* __restrict__ pos,
                       __half* __restrict__ kh)
{
    int idx = blockIdx.x * 256 + threadIdx.x;
    if (idx >= TT * KH * 64) return;
    int hh = idx & 63;
    int h  = (idx >> 6) % KH;
    int t  = idx / (64 * KH);

    float e   = (float)hh * (1.0f / 64.0f);
    float inv = 1.0f / powf(10000.0f, e);
    float ang = (float)pos[t] * inv;
    float s, c;
    sincosf(ang, &s, &c);

    size_t base = ((size_t)t * KH + h) * HD + hh;
    float x1 = src[base], x2 = src[base + 64];
    kh[base]      = __float2half_rn(x1 * c - x2 * s);
    kh[base + 64] = __float2half_rn(x2 * c + x1 * s);
}

__global__ void conv_h(const float* __restrict__ s, __half* __restrict__ d, int n4)
{
    int i = blockIdx.x * 256 + threadIdx.x;
    if (i >= n4) return;
    float4 f = ((const float4*)s)[i];
    __align__(8) __half h[4] = {__float2half_rn(f.x), __float2half_rn(f.y),
                                __float2half_rn(f.z), __float2half_rn(f.w)};
    *(uint2*)(d + 4 * (size_t)i) = *(uint2*)h;
}

// ====================== HMMA flash attention (causal, GQA) ======================
// CTA: 128 q rows x 1 head, 8 warps (16 q rows each). KV tiles of 64.
#define SRH 136
#define SRB 272
#define FL_SMEM ((128 * SRH + 4 * 64 * SRH) * 2)   // Qlo + 2 stages of (K,V)

__global__ __launch_bounds__(256) void flash_h(
    const __half* __restrict__ Qhi, const __half* __restrict__ Qlo,
    const __half* __restrict__ Kv,  const __half* __restrict__ Vv,
    __half* __restrict__ Oh, __half* __restrict__ Ol)
{
    extern __shared__ char fsm[];
    const uint32_t uQlo = smem_to_u32(fsm);
    const uint32_t uSt  = uQlo + 128 * SRB;

    const int tid = threadIdx.x, lane = tid & 31, wid = tid >> 5;
    const int qi = blockIdx.x, n = blockIdx.y, kvh = n >> 2;
    const int tq0 = qi * 128;
    const int ntiles = 2 * qi + 2;

    const __half* Qhg = Qhi + ((size_t)tq0 * NH + n) * HD;
    const __half* Qlg = Qlo + ((size_t)tq0 * NH + n) * HD;
    const __half* Kg  = Kv + (size_t)kvh * HD;
    const __half* Vg  = Vv + (size_t)kvh * HD;

    // ---- stage Qhi (into stage area) + Qlo (persistent) ----
    #pragma unroll
    for (int i = 0; i < 8; i++) {
        int c = tid + 256 * i;                 // 0..2047
        int row = c >> 4, c16 = c & 15;
        size_t go = (size_t)row * (NH * HD) + c16 * 8;
        CP16(uSt  + (uint32_t)row * SRB + c16 * 16, Qhg + go);
        CP16(uQlo + (uint32_t)row * SRB + c16 * 16, Qlg + go);
    }
    CP_COMMIT();
    CP_WAIT(0);
    __syncthreads();

    uint32_t qh[8][4];
    {
        const uint32_t qa = uSt + (uint32_t)(wid * 16 + (lane & 15)) * SRB
                          + (lane >> 4) * 16;
        #pragma unroll
        for (int dc = 0; dc < 8; dc++)
            LDSM4(qh[dc], qa + dc * 32);
    }
    __syncthreads();   // stage area free for KV

    const uint32_t qlA = uQlo + (uint32_t)(wid * 16 + (lane & 15)) * SRB
                       + (lane >> 4) * 16;
    const int l8 = lane & 7, ls8 = (lane >> 3) & 1;

    float o[16][4];
    #pragma unroll
    for (int i = 0; i < 16; i++)
        #pragma unroll
        for (int j = 0; j < 4; j++) o[i][j] = 0.f;
    float m0 = -1e30f, m1 = -1e30f, l0 = 0.f, l1 = 0.f;

    // preload tile 0
    #pragma unroll
    for (int i = 0; i < 4; i++) {
        int c = tid + 256 * i;
        int row = c >> 4, c16 = c & 15;
        size_t go = (size_t)row * (KH * HD) + c16 * 8;
        CP16(uSt + (uint32_t)row * SRB + c16 * 16, Kg + go);
        CP16(uSt + 64 * SRB + (uint32_t)row * SRB + c16 * 16, Vg + go);
    }
    CP_COMMIT();

    for (int t = 0; t < ntiles; t++) {
        if (t + 1 < ntiles) {
            uint32_t st = uSt + ((t + 1) & 1) * (2 * 64 * SRB);
            const int s0 = (t + 1) * 64;
            #pragma unroll
            for (int i = 0; i < 4; i++) {
                int c = tid + 256 * i;
                int row = c >> 4, c16 = c & 15;
                size_t go = (size_t)(s0 + row) * (KH * HD) + c16 * 8;
                CP16(st + (uint32_t)row * SRB + c16 * 16, Kg + go);
                CP16(st + 64 * SRB + (uint32_t)row * SRB + c16 * 16, Vg + go);
            }
            CP_COMMIT();
            CP_WAIT(1);
        } else {
            CP_WAIT(0);
        }
        __syncthreads();

        const uint32_t uK = uSt + (t & 1) * (2 * 64 * SRB);
        const uint32_t uV = uK + 64 * SRB;

        // ---- S = Q K^T ----  (K smem is [token][dim] == [N,K]: NON-trans B load)
        float s[8][4];
        #pragma unroll
        for (int nt = 0; nt < 8; nt++)
            #pragma unroll
            for (int j = 0; j < 4; j++) s[nt][j] = 0.f;

        #pragma unroll
        for (int dc = 0; dc < 8; dc++) {
            uint32_t ql[4];
            LDSM4(ql, qlA + dc * 32);
            #pragma unroll
            for (int nt = 0; nt < 8; nt++) {
                uint32_t bb[2];
                LDSM2(bb, uK + (uint32_t)(nt * 8 + l8) * SRB + (dc * 16 + ls8 * 8) * 2);
                MMAH(s[nt], qh[dc], bb);
                MMAH(s[nt], ql, bb);
            }
        }

        // ---- causal mask ----
        if (t >= 2 * qi) {
            const int r0 = tq0 + wid * 16 + (lane >> 2);
            const int cB = t * 64 + (lane & 3) * 2;
            #pragma unroll
            for (int nt = 0; nt < 8; nt++) {
                int c0 = cB + nt * 8;
                if (c0     > r0)     s[nt][0] = -1e30f;
                if (c0 + 1 > r0)     s[nt][1] = -1e30f;
                if (c0     > r0 + 8) s[nt][2] = -1e30f;
                if (c0 + 1 > r0 + 8) s[nt][3] = -1e30f;
            }
        }

        // ---- online softmax ----
        float mr0 = -1e30f, mr1 = -1e30f;
        #pragma unroll
        for (int nt = 0; nt < 8; nt++) {
            mr0 = fmaxf(mr0, fmaxf(s[nt][0], s[nt][1]));
            mr1 = fmaxf(mr1, fmaxf(s[nt][2], s[nt][3]));
        }
        mr0 = fmaxf(mr0, __shfl_xor_sync(0xffffffffu, mr0, 1));
        mr0 = fmaxf(mr0, __shfl_xor_sync(0xffffffffu, mr0, 2));
        mr1 = fmaxf(mr1, __shfl_xor_sync(0xffffffffu, mr1, 1));
        mr1 = fmaxf(mr1, __shfl_xor_sync(0xffffffffu, mr1, 2));

        const float mn0 = fmaxf(m0, mr0), mn1 = fmaxf(m1, mr1);
        const float a0 = __expf(m0 - mn0), a1 = __expf(m1 - mn1);
        m0 = mn0; m1 = mn1;

        float ls0 = 0.f, ls1 = 0.f;
        #pragma unroll
        for (int nt = 0; nt < 8; nt++) {
            s[nt][0] = __expf(s[nt][0] - m0); ls0 += s[nt][0];
            s[nt][1] = __expf(s[nt][1] - m0); ls0 += s[nt][1];
            s[nt][2] = __expf(s[nt][2] - m1); ls1 += s[nt][2];
            s[nt][3] = __expf(s[nt][3] - m1); ls1 += s[nt][3];
        }
        ls0 += __shfl_xor_sync(0xffffffffu, ls0, 1);
        ls0 += __shfl_xor_sync(0xffffffffu, ls0, 2);
        ls1 += __shfl_xor_sync(0xffffffffu, ls1, 1);
        ls1 += __shfl_xor_sync(0xffffffffu, ls1, 2);
        l0 = l0 * a0 + ls0;
        l1 = l1 * a1 + ls1;

        #pragma unroll
        for (int i = 0; i < 16; i++) {
            o[i][0] *= a0; o[i][1] *= a0; o[i][2] *= a1; o[i][3] *= a1;
        }

        // ---- P fragments (hi/lo fp16) ----
        uint32_t phi[4][4], plo[4][4];
        #pragma unroll
        for (int kc = 0; kc < 4; kc++) {
            #pragma unroll
            for (int q = 0; q < 4; q++) {
                int nt = 2 * kc + (q >> 1);
                float f0 = s[nt][(q & 1) * 2], f1 = s[nt][(q & 1) * 2 + 1];
                __half2 h = __floats2half2_rn(f0, f1);
                float2 hf = __half22float2(h);
                __half2 l = __floats2half2_rn(f0 - hf.x, f1 - hf.y);
                phi[kc][q] = *(uint32_t*)&h;
                plo[kc][q] = *(uint32_t*)&l;
            }
        }

        // ---- O += P V ----  (V smem is [token=k][dim=n]: trans B load)
        #pragma unroll
        for (int nt2 = 0; nt2 < 16; nt2++) {
            #pragma unroll
            for (int kc = 0; kc < 4; kc++) {
                uint32_t bb[2];
                LDSM2T(bb, uV + (uint32_t)(kc * 16 + ls8 * 8 + l8) * SRB + nt2 * 16);
                MMAH(o[nt2], phi[kc], bb);
                MMAH(o[nt2], plo[kc], bb);
            }
        }
        __syncthreads();
    }

    // ---- epilogue: O / l, write fp16 hi/lo ----
    const float i0 = 1.f / l0, i1 = 1.f / l1;
    const int r0 = tq0 + wid * 16 + (lane >> 2);
    const int cofs = (lane & 3) * 2;
    #pragma unroll
    for (int nt2 = 0; nt2 < 16; nt2++) {
        float v0 = o[nt2][0] * i0, v1 = o[nt2][1] * i0;
        float v2 = o[nt2][2] * i1, v3 = o[nt2][3] * i1;
        size_t p0 = ((size_t)r0 * NH + n) * HD + nt2 * 8 + cofs;
        size_t p1 = ((size_t)(r0 + 8) * NH + n) * HD + nt2 * 8 + cofs;
        __half2 h0 = __floats2half2_rn(v0, v1);
        float2 hf0 = __half22float2(h0);
        __half2 l0h = __floats2half2_rn(v0 - hf0.x, v1 - hf0.y);
        __half2 h1 = __floats2half2_rn(v2, v3);
        float2 hf1 = __half22float2(h1);
        __half2 l1h = __floats2half2_rn(v2 - hf1.x, v3 - hf1.y);
        *(__half2*)(Oh + p0) = h0;  *(__half2*)(Ol + p0) = l0h;
        *(__half2*)(Oh + p1) = h1;  *(__half2*)(Ol + p1) = l1h;
    }
}

// ====================== launch ======================
extern "C" void kernel_launch(void* const* d_in, const int* in_sizes, int n_in,
                              void* d_out, int out_size)
{
    const float* x   = (const float*)d_in[0];
    const int*   pos = (const int*)  d_in[1];
    const float* w_q = (const float*)d_in[2];
    const float* w_k = (const float*)d_in[3];
    const float* w_v = (const float*)d_in[4];
    const float* w_o = (const float*)d_in[5];
    float* out = (float*)d_out;

    float *q, *k, *v;
    cudaGetSymbolAddress((void**)&q, g_q);
    cudaGetSymbolAddress((void**)&k, g_k);
    cudaGetSymbolAddress((void**)&v, g_v);
    __half *xh, *xl, *aoh, *aol, *wqT, *wkT, *wvT, *woT, *qh, *ql, *kh, *vh;
    cudaGetSymbolAddress((void**)&xh,  g_xh);  cudaGetSymbolAddress((void**)&xl,  g_xl);
    cudaGetSymbolAddress((void**)&aoh, g_aoh); cudaGetSymbolAddress((void**)&aol, g_aol);
    cudaGetSymbolAddress((void**)&wqT, g_wqT); cudaGetSymbolAddress((void**)&wkT, g_wkT);
    cudaGetSymbolAddress((void**)&wvT, g_wvT); cudaGetSymbolAddress((void**)&woT, g_woT);
    cudaGetSymbolAddress((void**)&qh,  g_qh);  cudaGetSymbolAddress((void**)&ql,  g_ql);
    cudaGetSymbolAddress((void**)&kh,  g_kh);  cudaGetSymbolAddress((void**)&vh,  g_vh);

    cudaFuncSetAttribute(gemm_fh2, cudaFuncAttributeMaxDynamicSharedMemorySize, GEMM_SMEM);
    cudaFuncSetAttribute(flash_h,  cudaFuncAttributeMaxDynamicSharedMemorySize, FL_SMEM);

    // operand prep
    split_f32h<<<(TT*DD/4 + 255)/256, 256>>>(x, xh, xl, TT*DD/4);
    transT_f16<<<dim3(DD/32, DD/32),    256>>>(w_q, wqT, DD, DD);
    transT_f16<<<dim3(KH*HD/32, DD/32), 256>>>(w_k, wkT, DD, KH*HD);
    transT_f16<<<dim3(KH*HD/32, DD/32), 256>>>(w_v, wvT, DD, KH*HD);
    transT_f16<<<dim3(DD/32, DD/32),    256>>>(w_o, woT, DD, DD);

    // QKV projections
    gemm_fh2<<<dim3(32, 16), 256, GEMM_SMEM>>>(xh, xl, wqT, q, TT, NH*HD, DD);
    gemm_fh2<<<dim3(8, 16),  256, GEMM_SMEM>>>(xh, xl, wkT, k, TT, KH*HD, DD);
    gemm_fh2<<<dim3(8, 16),  256, GEMM_SMEM>>>(xh, xl, wvT, v, TT, KH*HD, DD);

    // RoPE + fp16 conversions
    rope_q<<<(TT*NH*64 + 255)/256, 256>>>(q, pos, qh, ql);
    rope_k<<<(TT*KH*64 + 255)/256, 256>>>(k, pos, kh);
    conv_h<<<(TT*KH*HD/4 + 255)/256, 256>>>(v, vh, TT*KH*HD/4);

    // causal GQA flash attention (HMMA) -> fp16 hi/lo attention output
    flash_h<<<dim3(TT/128, NH), 256, FL_SMEM>>>(qh, ql, kh, vh, aoh, aol);

    // output projection
    gemm_fh2<<<dim3(32, 16), 256, GEMM_SMEM>>>(aoh, aol, woT, out, TT, DD, DD);
}